// round 7
// baseline (speedup 1.0000x reference)
#include <cuda_runtime.h>
#include <cuda_bf16.h>
#include <math.h>
#include <stdint.h>

// ---------------- problem constants ----------------
#define B_   512
#define NW   64
#define NQ   343
#define NTOK 344
#define NP   352
#define DIM  96
#define H    3
#define HD   32
#define NROWS (B_*NTOK)
#define XOUT_SZ ((size_t)B_*NQ*DIM)

// ---------------- scratch ----------------
__device__ float g_att[(size_t)B_*NTOK*DIM];
__device__ float g_bm[(size_t)H*NW*NQ*NQ];   // bias[h] + mask[w]

// ---------------- kernel 0: bm = bias gather + mask ----------------
__global__ void bm_pre_kernel(const float* __restrict__ btab,
                              const int* __restrict__ ri,
                              const float* __restrict__ mask) {
    size_t gid = (size_t)blockIdx.x * 256 + threadIdx.x;
    if (gid >= (size_t)H*NW*NQ*NQ) return;
    int i  = (int)(gid % (NQ*NQ));
    int hw = (int)(gid / (NQ*NQ));
    int h = hw / NW, w = hw % NW;
    g_bm[gid] = btab[ri[i]*H + h] + mask[(size_t)w*NQ*NQ + i];
}

// ---------------- helpers ----------------
__device__ __forceinline__ uint32_t pack_bf16(float lo, float hi) {
    uint32_t r;
    asm("cvt.rn.bf16x2.f32 %0, %1, %2;" : "=r"(r) : "f"(hi), "f"(lo));
    return r;
}

#define MMA_BF16(d, a0,a1,a2,a3, b0,b1)                                      \
    asm volatile("mma.sync.aligned.m16n8k16.row.col.f32.bf16.bf16.f32 "      \
        "{%0,%1,%2,%3},{%4,%5,%6,%7},{%8,%9},{%0,%1,%2,%3};"                 \
        : "+f"(d[0]), "+f"(d[1]), "+f"(d[2]), "+f"(d[3])                      \
        : "r"(a0), "r"(a1), "r"(a2), "r"(a3), "r"(b0), "r"(b1))

// ---------------- fused qkv-GEMM + flash attention ----------------
// block = (b,h): 22 warps. GEMM: each warp one m16 row tile of 352 rows,
// 12 n8 tiles (Q|K|V dims), 6 k16 tiles. Epilogue writes attn smem layouts.
// smem u32 words:
//   Xp[352][52] | Wp[48][104] | bias[96+8] | Qp[352][20] | Ktp[16][360] | Vb bf16[32][360]
#define SM_XP 0
#define SM_WP 18304
#define SM_BS 23296
#define SM_QP 23400
#define SM_KT 30440
#define SM_VB 36200
#define FUSED_SMEM ((36200 + 5760) * 4)   // 167840 B

__global__ void __launch_bounds__(704, 1)
fused_attn_kernel(const float* __restrict__ x,
                  const float* __restrict__ gt,
                  const float* __restrict__ Wqkv,
                  const float* __restrict__ bqkv) {
    extern __shared__ uint32_t smu[];
    uint32_t* Xp  = smu + SM_XP;            // [352][52]  x pairs along k
    uint32_t* Wp  = smu + SM_WP;            // [48][104]  W pairs: [k2][outcol]
    float*    bis = (float*)(smu + SM_BS);  // [96]
    uint32_t* Qp  = smu + SM_QP;            // [352][20]  q pairs along d (scaled)
    uint32_t* Ktp = smu + SM_KT;            // [16][360]  k pairs: [d2][token]
    uint32_t* Vb  = smu + SM_VB;            // bf16 [32][360] viewed as u32 [32][180]
    __nv_bfloat16* Vbh = (__nv_bfloat16*)Vb;

    // bid remap: 8 consecutive blocks share one (h,w) bm slice
    const int bid = blockIdx.x;
    const int rep = bid & 7;
    const int hw  = bid >> 3;
    const int w   = hw & 63;
    const int h   = hw >> 6;
    const int b   = (rep << 6) + w;

    const int tid  = threadIdx.x;
    const int wid  = tid >> 5;
    const int lane = tid & 31;
    const int g    = lane >> 2;
    const int tg   = lane & 3;
    const float scale = 0.17677669529663687f;

    // ---- fill Xp (xc rows, bf16 pairs), zero-pad rows 344..351 ----
    for (int idx = tid; idx < 352*48; idx += 704) {
        int n = idx / 48, p = idx % 48;
        float a = 0.f, c = 0.f;
        if (n < NTOK) {
            const float* src = (n == 0) ? (gt + (size_t)b*DIM)
                                        : (x + ((size_t)b*NQ + (n-1))*DIM);
            float2 v2 = *(const float2*)(src + 2*p);
            a = v2.x; c = v2.y;
        }
        Xp[n*52 + p] = pack_bf16(a, c);
    }
    // ---- fill Wp: out-col c -> Wqkv row for head h; pairs along k ----
    for (int idx = tid; idx < 48*96; idx += 704) {
        int k2 = idx / 96, c = idx % 96;
        int row = (c < 32) ? (h*HD + c)
                : (c < 64) ? (DIM + h*HD + (c-32))
                           : (2*DIM + h*HD + (c-64));
        const float* wr = Wqkv + (size_t)row*DIM + 2*k2;
        Wp[k2*104 + c] = pack_bf16(wr[0], wr[1]);
    }
    if (tid < 96) {
        int c = tid;
        int row = (c < 32) ? (h*HD + c)
                : (c < 64) ? (DIM + h*HD + (c-32))
                           : (2*DIM + h*HD + (c-64));
        bis[c] = bqkv[row];
    }
    __syncthreads();

    // ---- GEMM: warp owns rows mb..mb+15 ----
    const int mb = wid * 16;
    {
        uint32_t xa[6][4];
        #pragma unroll
        for (int kt = 0; kt < 6; ++kt) {
            xa[kt][0] = Xp[(mb+g)*52   + kt*8 + tg];
            xa[kt][1] = Xp[(mb+g+8)*52 + kt*8 + tg];
            xa[kt][2] = Xp[(mb+g)*52   + kt*8 + tg + 4];
            xa[kt][3] = Xp[(mb+g+8)*52 + kt*8 + tg + 4];
        }
        #pragma unroll
        for (int nt = 0; nt < 12; ++nt) {
            float c4[4] = {0.f, 0.f, 0.f, 0.f};
            #pragma unroll
            for (int kt = 0; kt < 6; ++kt) {
                uint32_t b0 = Wp[(kt*8 + tg)*104     + nt*8 + g];
                uint32_t b1 = Wp[(kt*8 + tg + 4)*104 + nt*8 + g];
                MMA_BF16(c4, xa[kt][0], xa[kt][1], xa[kt][2], xa[kt][3], b0, b1);
            }
            float bia = bis[nt*8 + 2*tg];
            float bib = bis[nt*8 + 2*tg + 1];
            c4[0] += bia; c4[1] += bib; c4[2] += bia; c4[3] += bib;
            int sec = nt >> 2, ntr = nt & 3;
            if (sec == 0) {
                Qp[(mb+g)*20   + ntr*4 + tg] = pack_bf16(c4[0]*scale, c4[1]*scale);
                Qp[(mb+g+8)*20 + ntr*4 + tg] = pack_bf16(c4[2]*scale, c4[3]*scale);
            } else if (sec == 1) {
                Ktp[(ntr*4 + tg)*360 + mb + g]     = pack_bf16(c4[0], c4[1]);
                Ktp[(ntr*4 + tg)*360 + mb + g + 8] = pack_bf16(c4[2], c4[3]);
            } else {
                int d = ntr*8 + 2*tg;
                Vbh[(size_t)d*360     + mb + g]     = __float2bfloat16(c4[0]);
                Vbh[(size_t)(d+1)*360 + mb + g]     = __float2bfloat16(c4[1]);
                Vbh[(size_t)d*360     + mb + g + 8] = __float2bfloat16(c4[2]);
                Vbh[(size_t)(d+1)*360 + mb + g + 8] = __float2bfloat16(c4[3]);
            }
        }
    }
    __syncthreads();

    // ---- attention: warp owns queries mb..mb+15 ----
    const float* bmb = g_bm + ((size_t)(h*NW + w)) * NQ * NQ;
    const int rl = mb + g;

    uint32_t qf[2][4];
    #pragma unroll
    for (int kd = 0; kd < 2; ++kd) {
        qf[kd][0] = Qp[rl*20     + kd*8 + tg];
        qf[kd][1] = Qp[(rl+8)*20 + kd*8 + tg];
        qf[kd][2] = Qp[rl*20     + kd*8 + tg + 4];
        qf[kd][3] = Qp[(rl+8)*20 + kd*8 + tg + 4];
    }

    float o[4][4];
    float l[2] = {0.f, 0.f};
    #pragma unroll
    for (int nt = 0; nt < 4; ++nt)
        #pragma unroll
        for (int e = 0; e < 4; ++e) o[nt][e] = 0.f;

    #pragma unroll 1
    for (int kb = 0; kb < 11; ++kb) {
        const int kbase = kb*32;

        float s[4][4];
        #pragma unroll
        for (int nt = 0; nt < 4; ++nt)
            #pragma unroll
            for (int e = 0; e < 4; ++e) s[nt][e] = 0.f;

        #pragma unroll
        for (int kd = 0; kd < 2; ++kd) {
            #pragma unroll
            for (int nt = 0; nt < 4; ++nt) {
                uint32_t b0 = Ktp[(kd*8 + tg)*360     + kbase + nt*8 + g];
                uint32_t b1 = Ktp[(kd*8 + tg + 4)*360 + kbase + nt*8 + g];
                MMA_BF16(s[nt], qf[kd][0], qf[kd][1], qf[kd][2], qf[kd][3], b0, b1);
            }
        }

        #pragma unroll
        for (int rr = 0; rr < 2; ++rr) {
            int n0 = rl + rr*8;
            bool vq = (n0 >= 1) && (n0 < NTOK);
            const float* bmrow = bmb + (size_t)(vq ? (n0-1) : 0) * NQ;
            float lv = 0.f;
            #pragma unroll
            for (int nt = 0; nt < 4; ++nt)
                #pragma unroll
                for (int e = 0; e < 2; ++e) {
                    int j = kbase + nt*8 + 2*tg + e;
                    float p;
                    if (j >= NTOK) p = 0.f;
                    else {
                        float add = (vq && j >= 1) ? __ldg(bmrow + j - 1) : 0.f;
                        p = __expf(s[nt][rr*2+e] + add);
                    }
                    lv += p;
                    s[nt][rr*2+e] = p;
                }
            l[rr] += lv;
        }

        #pragma unroll
        for (int kk = 0; kk < 2; ++kk) {
            uint32_t a0 = pack_bf16(s[2*kk][0],   s[2*kk][1]);
            uint32_t a1 = pack_bf16(s[2*kk][2],   s[2*kk][3]);
            uint32_t a2 = pack_bf16(s[2*kk+1][0], s[2*kk+1][1]);
            uint32_t a3 = pack_bf16(s[2*kk+1][2], s[2*kk+1][3]);
            #pragma unroll
            for (int nt = 0; nt < 4; ++nt) {
                int d = nt*8 + g;
                uint32_t b0 = Vb[d*180 + kb*16 + kk*8 + tg];
                uint32_t b1 = Vb[d*180 + kb*16 + kk*8 + tg + 4];
                MMA_BF16(o[nt], a0, a1, a2, a3, b0, b1);
            }
        }
    }

    #pragma unroll
    for (int rr = 0; rr < 2; ++rr) {
        float lv = l[rr];
        lv += __shfl_xor_sync(0xffffffffu, lv, 1);
        lv += __shfl_xor_sync(0xffffffffu, lv, 2);
        float inv = 1.f / lv;
        int n0 = rl + rr*8;
        if (n0 < NTOK) {
            float* dst = g_att + ((size_t)b*NTOK + n0)*DIM + h*HD;
            #pragma unroll
            for (int nt = 0; nt < 4; ++nt)
                *(float2*)(dst + nt*8 + 2*tg) =
                    make_float2(o[nt][rr*2]*inv, o[nt][rr*2+1]*inv);
        }
    }
}

// ---------------- kernel 3: proj + scatter ----------------
#define GEMM_SMEM ((128*100 + 96*100) * 4)
__global__ void __launch_bounds__(256, 2)
proj_kernel(const float* __restrict__ W,
            const float* __restrict__ bp,
            float* __restrict__ dout) {
    extern __shared__ float sm[];
    float* Asm = sm;              // [128][100]
    float* Wsm = sm + 128*100;    // [96][100]
    const int tid  = threadIdx.x;
    const int row0 = blockIdx.x * 128;

    for (int idx = tid; idx < 128*24; idx += 256) {
        int r = idx / 24, c4 = idx % 24;
        *(float4*)&Asm[r*100 + c4*4] =
            *(const float4*)(g_att + (size_t)(row0 + r)*DIM + c4*4);
    }
    for (int idx = tid; idx < 96*24; idx += 256) {
        int r = idx / 24, c4 = idx % 24;
        *(float4*)&Wsm[r*100 + c4*4] = *(const float4*)(W + (size_t)r*96 + c4*4);
    }
    __syncthreads();

    const int tx = tid % 16;
    const int ty = tid / 16;
    float acc[8][6];
    #pragma unroll
    for (int i = 0; i < 8; ++i)
        #pragma unroll
        for (int j = 0; j < 6; ++j) acc[i][j] = 0.f;

    #pragma unroll 2
    for (int k = 0; k < 96; k += 4) {
        float4 a4[8], w4[6];
        #pragma unroll
        for (int i = 0; i < 8; ++i) a4[i] = *(const float4*)&Asm[(ty*8+i)*100 + k];
        #pragma unroll
        for (int j = 0; j < 6; ++j) w4[j] = *(const float4*)&Wsm[(tx*6+j)*100 + k];
        #pragma unroll
        for (int i = 0; i < 8; ++i)
            #pragma unroll
            for (int j = 0; j < 6; ++j)
                acc[i][j] += a4[i].x*w4[j].x + a4[i].y*w4[j].y
                           + a4[i].z*w4[j].z + a4[i].w*w4[j].w;
    }

    #pragma unroll
    for (int i = 0; i < 8; ++i) {
        int gr = row0 + ty*8 + i;
        int b = gr / NTOK, n = gr % NTOK;
        #pragma unroll
        for (int j = 0; j < 6; ++j) {
            int c = tx*6 + j;
            float v = acc[i][j] + bp[c];
            if (n == 0) dout[XOUT_SZ + (size_t)b*DIM + c] = v;
            else        dout[((size_t)b*NQ + (n-1))*DIM + c] = v;
        }
    }
}

// ---------------- launch ----------------
extern "C" void kernel_launch(void* const* d_in, const int* in_sizes, int n_in,
                              void* d_out, int out_size) {
    const float* x     = (const float*)d_in[0];
    const float* gt    = (const float*)d_in[1];
    const float* mask  = (const float*)d_in[2];
    const int*   ri    = (const int*)  d_in[3];
    const float* Wqkv  = (const float*)d_in[4];
    const float* bqkv  = (const float*)d_in[5];
    const float* Wproj = (const float*)d_in[6];
    const float* bproj = (const float*)d_in[7];
    const float* btab  = (const float*)d_in[8];
    float* out = (float*)d_out;

    cudaFuncSetAttribute(fused_attn_kernel, cudaFuncAttributeMaxDynamicSharedMemorySize, FUSED_SMEM);
    cudaFuncSetAttribute(proj_kernel,       cudaFuncAttributeMaxDynamicSharedMemorySize, GEMM_SMEM);

    {
        size_t total = (size_t)H*NW*NQ*NQ;
        bm_pre_kernel<<<(unsigned)((total + 255)/256), 256>>>(btab, ri, mask);
    }
    fused_attn_kernel<<<B_*H, 704, FUSED_SMEM>>>(x, gt, Wqkv, bqkv);
    proj_kernel<<<NROWS/128, 256, GEMM_SMEM>>>(Wproj, bproj, out);
}

// round 9
// speedup vs baseline: 1.0546x; 1.0546x over previous
#include <cuda_runtime.h>
#include <cuda_bf16.h>
#include <math.h>
#include <stdint.h>

#define B_   512
#define NW   64
#define NQ   343
#define NTOK 344
#define DIM  96
#define H    3
#define HD   32
#define NROWS (B_*NTOK)
#define XOUT_SZ ((size_t)B_*NQ*DIM)
#define BMSTR 344

typedef unsigned long long u64;

__device__ float g_att[(size_t)B_*NTOK*DIM];
__device__ float g_bm[(size_t)H*NW*NQ*BMSTR + 16];   // +16 pad: float4 reads past last row

// ---------------- kernel 0: bm gather (stride 344, col0 = 0) ----------------
__global__ void bm_pre_kernel(const float* __restrict__ btab,
                              const int* __restrict__ ri,
                              const float* __restrict__ mask) {
    size_t gid = (size_t)blockIdx.x * 256 + threadIdx.x;
    if (gid >= (size_t)H*NW*NQ*BMSTR) return;
    int i  = (int)(gid % (NQ*BMSTR));
    int hw = (int)(gid / (NQ*BMSTR));
    int h = hw / NW, w = hw % NW;
    int r = i / BMSTR, j = i % BMSTR;
    float v = 0.f;
    if (j >= 1)
        v = btab[ri[r*NQ + (j-1)]*H + h] + mask[(size_t)w*NQ*NQ + r*NQ + (j-1)];
    g_bm[gid] = v;
}

// ---------------- helpers ----------------
__device__ __forceinline__ uint32_t pack_bf16(float lo, float hi) {
    uint32_t r;
    asm("cvt.rn.bf16x2.f32 %0, %1, %2;" : "=r"(r) : "f"(hi), "f"(lo));
    return r;
}
__device__ __forceinline__ u64 pk2(float lo, float hi) {
    u64 r; asm("mov.b64 %0, {%1, %2};" : "=l"(r) : "f"(lo), "f"(hi)); return r;
}
__device__ __forceinline__ void upk2(float& lo, float& hi, u64 v) {
    asm("mov.b64 {%0, %1}, %2;" : "=f"(lo), "=f"(hi) : "l"(v));
}
__device__ __forceinline__ void fma2(u64& d, u64 a, u64 b) {
    asm("fma.rn.f32x2 %0, %1, %2, %3;" : "=l"(d) : "l"(a), "l"(b), "l"(d));
}

#define MMA_BF16(d, a0,a1,a2,a3, b0,b1)                                      \
    asm volatile("mma.sync.aligned.m16n8k16.row.col.f32.bf16.bf16.f32 "      \
        "{%0,%1,%2,%3},{%4,%5,%6,%7},{%8,%9},{%0,%1,%2,%3};"                 \
        : "+f"(d[0]), "+f"(d[1]), "+f"(d[2]), "+f"(d[3])                      \
        : "r"(a0), "r"(a1), "r"(a2), "r"(a3), "r"(b0), "r"(b1))

// smem layout (bytes)
#define SM_XP   0          // phase1: u32[352][26] = 36608  (aliased by P in phase2)
#define SM_WP   36608      // phase1: u32[48][104] = 19968
#define SM_BS   56576      // phase1: f32[96]
#define SM_QS   56960      // f32 [176 pairs][68]  = 47872  (q interleaved pairs)
#define SM_KT   104832     // f32 [32][356]        = 45568
#define SM_VS   150400     // f32 [352][36]        = 50688
#define FUSED_SMEM 201088
// P (phase2): u64 per warp [8 pair-rows][33], base = warp*2112 bytes, region [0, 46464)

__global__ void __launch_bounds__(704, 1)
fused_attn_kernel(const float* __restrict__ x,
                  const float* __restrict__ gt,
                  const float* __restrict__ Wqkv,
                  const float* __restrict__ bqkv) {
    extern __shared__ char smem[];
    uint32_t* Xp = (uint32_t*)(smem + SM_XP);
    uint32_t* Wp = (uint32_t*)(smem + SM_WP);
    float* bis = (float*)(smem + SM_BS);
    float* Qs  = (float*)(smem + SM_QS);
    float* Kt  = (float*)(smem + SM_KT);
    float* Vs  = (float*)(smem + SM_VS);

    const int bid = blockIdx.x;
    const int rep = bid & 7;
    const int hw  = bid >> 3;
    const int w   = hw & 63;
    const int h   = hw >> 6;
    const int b   = (rep << 6) + w;

    const int tid  = threadIdx.x;
    const int wid  = tid >> 5;
    const int lane = tid & 31;
    const int g    = lane >> 2;
    const int tg   = lane & 3;
    const int tq   = lane >> 3;     // phase2: 4 q-slots
    const int tk   = lane & 7;      // phase2: 8 k/d-slots
    const float scale = 0.17677669529663687f;

    // ---- W and bias fill (once) ----
    for (int idx = tid; idx < 48*96; idx += 704) {
        int k2 = idx / 96, c = idx % 96;
        int row = (c < 32) ? (h*HD + c)
                : (c < 64) ? (DIM + h*HD + (c-32))
                           : (2*DIM + h*HD + (c-64));
        const float* wr = Wqkv + (size_t)row*DIM + 2*k2;
        Wp[k2*104 + c] = pack_bf16(wr[0], wr[1]);
    }
    if (tid < 96) {
        int c = tid;
        int row = (c < 32) ? (h*HD + c)
                : (c < 64) ? (DIM + h*HD + (c-32))
                           : (2*DIM + h*HD + (c-64));
        bis[c] = bqkv[row];
    }

    // ---- phase 1: two-pass bf16 MMA GEMM over k ----
    const int mb = wid * 16;
    float c4[12][4];
    #pragma unroll
    for (int nt = 0; nt < 12; ++nt)
        #pragma unroll
        for (int e = 0; e < 4; ++e) c4[nt][e] = 0.f;

    for (int pass = 0; pass < 2; ++pass) {
        if (pass) __syncthreads();          // prior pass reads done
        for (int idx = tid; idx < 352*24; idx += 704) {
            int n = idx / 24, p = idx % 24;
            float a = 0.f, cc = 0.f;
            if (n < NTOK) {
                const float* src = (n == 0) ? (gt + (size_t)b*DIM)
                                            : (x + ((size_t)b*NQ + (n-1))*DIM);
                float2 v2 = *(const float2*)(src + pass*48 + 2*p);
                a = v2.x; cc = v2.y;
            }
            Xp[n*26 + p] = pack_bf16(a, cc);
        }
        __syncthreads();
        uint32_t xa[3][4];
        #pragma unroll
        for (int kt = 0; kt < 3; ++kt) {
            xa[kt][0] = Xp[(mb+g)*26   + kt*8 + tg];
            xa[kt][1] = Xp[(mb+g+8)*26 + kt*8 + tg];
            xa[kt][2] = Xp[(mb+g)*26   + kt*8 + tg + 4];
            xa[kt][3] = Xp[(mb+g+8)*26 + kt*8 + tg + 4];
        }
        #pragma unroll
        for (int nt = 0; nt < 12; ++nt)
            #pragma unroll
            for (int kt = 0; kt < 3; ++kt) {
                int kr = (pass*3 + kt)*8 + tg;
                uint32_t b0 = Wp[kr*104 + nt*8 + g];
                uint32_t b1 = Wp[(kr+4)*104 + nt*8 + g];
                MMA_BF16(c4[nt], xa[kt][0], xa[kt][1], xa[kt][2], xa[kt][3], b0, b1);
            }
    }
    // epilogue: f32 Q (pair-interleaved) / Kt / V
    #pragma unroll
    for (int nt = 0; nt < 12; ++nt) {
        float bia = bis[nt*8 + 2*tg];
        float bib = bis[nt*8 + 2*tg + 1];
        float v0 = c4[nt][0] + bia, v1 = c4[nt][1] + bib;
        float v2 = c4[nt][2] + bia, v3 = c4[nt][3] + bib;
        const int sec = nt >> 2, ntr = nt & 3;
        const int d0 = ntr*8 + 2*tg;
        const int n1 = mb + g, n2 = n1 + 8;
        if (sec == 0) {
            Qs[(n1>>1)*68 + d0*2     + (n1&1)] = v0*scale;
            Qs[(n1>>1)*68 + (d0+1)*2 + (n1&1)] = v1*scale;
            Qs[(n2>>1)*68 + d0*2     + (n2&1)] = v2*scale;
            Qs[(n2>>1)*68 + (d0+1)*2 + (n2&1)] = v3*scale;
        } else if (sec == 1) {
            Kt[d0*356 + n1] = v0; Kt[(d0+1)*356 + n1] = v1;
            Kt[d0*356 + n2] = v2; Kt[(d0+1)*356 + n2] = v3;
        } else {
            Vs[n1*36 + d0] = v0; Vs[n1*36 + d0 + 1] = v1;
            Vs[n2*36 + d0] = v2; Vs[n2*36 + d0 + 1] = v3;
        }
    }
    __syncthreads();

    // ---- phase 2: f32x2 attention; warp owns 16 queries ----
    u64* Pw = (u64*)(smem + wid*2112);      // [8 pair-rows][33] u64
    const float* bmb = g_bm + ((size_t)(h*NW + w)) * NQ * BMSTR;
    const int q0 = mb + tq*4;               // thread's first q row (even)
    const int pr0 = tq*2;

    u64 o2[2][4];
    float l4[4] = {0.f, 0.f, 0.f, 0.f};
    #pragma unroll
    for (int p = 0; p < 2; ++p)
        #pragma unroll
        for (int c = 0; c < 4; ++c) o2[p][c] = pk2(0.f, 0.f);

    for (int kb = 0; kb < 11; ++kb) {
        const int kbase = kb*32;

        // S = Q K^T
        u64 acc2[2][4];
        #pragma unroll
        for (int p = 0; p < 2; ++p)
            #pragma unroll
            for (int c = 0; c < 4; ++c) acc2[p][c] = pk2(0.f, 0.f);

        const float* kp = Kt + kbase + tk*4;
        const float* qp = Qs + (q0>>1)*68;
        #pragma unroll 8
        for (int d = 0; d < 32; ++d) {
            u64 qa = *(const u64*)(qp + 2*d);
            u64 qb = *(const u64*)(qp + 68 + 2*d);
            float4 kv = *(const float4*)(kp + d*356);
            u64 k20 = pk2(kv.x, kv.x), k21 = pk2(kv.y, kv.y);
            u64 k22 = pk2(kv.z, kv.z), k23 = pk2(kv.w, kv.w);
            fma2(acc2[0][0], qa, k20); fma2(acc2[0][1], qa, k21);
            fma2(acc2[0][2], qa, k22); fma2(acc2[0][3], qa, k23);
            fma2(acc2[1][0], qb, k20); fma2(acc2[1][1], qb, k21);
            fma2(acc2[1][2], qb, k22); fma2(acc2[1][3], qb, k23);
        }

        // exp + bm; stage P pairs
        #pragma unroll
        for (int p = 0; p < 2; ++p) {
            int re = q0 + 2*p, ro = re + 1;
            bool ve = (re >= 1) && (re < NTOK);
            bool vo = (ro < NTOK);
            float4 bme = ve ? __ldg((const float4*)(bmb + (size_t)(re-1)*BMSTR + kbase + tk*4))
                            : make_float4(0.f,0.f,0.f,0.f);
            float4 bmo = vo ? __ldg((const float4*)(bmb + (size_t)(ro-1)*BMSTR + kbase + tk*4))
                            : make_float4(0.f,0.f,0.f,0.f);
            float be[4] = {bme.x, bme.y, bme.z, bme.w};
            float bo[4] = {bmo.x, bmo.y, bmo.z, bmo.w};
            #pragma unroll
            for (int c = 0; c < 4; ++c) {
                float se, so;
                upk2(se, so, acc2[p][c]);
                int j = kbase + tk*4 + c;
                float pe = (j < NTOK) ? __expf(se + be[c]) : 0.f;
                float po = (j < NTOK) ? __expf(so + bo[c]) : 0.f;
                l4[2*p]   += pe;
                l4[2*p+1] += po;
                Pw[(pr0 + p)*33 + tk*4 + c] = pk2(pe, po);
            }
        }
        __syncwarp();

        // O += P V
        const float* vp = Vs + (size_t)kbase*36 + tk*4;
        #pragma unroll 8
        for (int j = 0; j < 32; ++j) {
            u64 p20 = Pw[pr0*33 + j];
            u64 p21 = Pw[(pr0+1)*33 + j];
            float4 vv = *(const float4*)(vp + j*36);
            u64 v20 = pk2(vv.x, vv.x), v21 = pk2(vv.y, vv.y);
            u64 v22 = pk2(vv.z, vv.z), v23 = pk2(vv.w, vv.w);
            fma2(o2[0][0], p20, v20); fma2(o2[0][1], p20, v21);
            fma2(o2[0][2], p20, v22); fma2(o2[0][3], p20, v23);
            fma2(o2[1][0], p21, v20); fma2(o2[1][1], p21, v21);
            fma2(o2[1][2], p21, v22); fma2(o2[1][3], p21, v23);
        }
        __syncwarp();
    }

    // reduce l over tk group, normalize, store
    #pragma unroll
    for (int a = 0; a < 4; ++a) {
        l4[a] += __shfl_xor_sync(0xffffffffu, l4[a], 1);
        l4[a] += __shfl_xor_sync(0xffffffffu, l4[a], 2);
        l4[a] += __shfl_xor_sync(0xffffffffu, l4[a], 4);
    }
    #pragma unroll
    for (int p = 0; p < 2; ++p) {
        float oe[4], oo[4];
        #pragma unroll
        for (int c = 0; c < 4; ++c) upk2(oe[c], oo[c], o2[p][c]);
        int re = q0 + 2*p, ro = re + 1;
        if (re < NTOK) {
            float inv = 1.f / l4[2*p];
            *(float4*)(g_att + ((size_t)b*NTOK + re)*DIM + h*HD + tk*4) =
                make_float4(oe[0]*inv, oe[1]*inv, oe[2]*inv, oe[3]*inv);
        }
        if (ro < NTOK) {
            float inv = 1.f / l4[2*p+1];
            *(float4*)(g_att + ((size_t)b*NTOK + ro)*DIM + h*HD + tk*4) =
                make_float4(oo[0]*inv, oo[1]*inv, oo[2]*inv, oo[3]*inv);
        }
    }
}

// ---------------- proj + scatter (unchanged) ----------------
#define GEMM_SMEM ((128*100 + 96*100) * 4)
__global__ void __launch_bounds__(256, 2)
proj_kernel(const float* __restrict__ W,
            const float* __restrict__ bp,
            float* __restrict__ dout) {
    extern __shared__ float sm[];
    float* Asm = sm;
    float* Wsm = sm + 128*100;
    const int tid  = threadIdx.x;
    const int row0 = blockIdx.x * 128;

    for (int idx = tid; idx < 128*24; idx += 256) {
        int r = idx / 24, c4 = idx % 24;
        *(float4*)&Asm[r*100 + c4*4] =
            *(const float4*)(g_att + (size_t)(row0 + r)*DIM + c4*4);
    }
    for (int idx = tid; idx < 96*24; idx += 256) {
        int r = idx / 24, c4 = idx % 24;
        *(float4*)&Wsm[r*100 + c4*4] = *(const float4*)(W + (size_t)r*96 + c4*4);
    }
    __syncthreads();

    const int tx = tid % 16;
    const int ty = tid / 16;
    float acc[8][6];
    #pragma unroll
    for (int i = 0; i < 8; ++i)
        #pragma unroll
        for (int j = 0; j < 6; ++j) acc[i][j] = 0.f;

    #pragma unroll 2
    for (int k = 0; k < 96; k += 4) {
        float4 a4[8], w4[6];
        #pragma unroll
        for (int i = 0; i < 8; ++i) a4[i] = *(const float4*)&Asm[(ty*8+i)*100 + k];
        #pragma unroll
        for (int j = 0; j < 6; ++j) w4[j] = *(const float4*)&Wsm[(tx*6+j)*100 + k];
        #pragma unroll
        for (int i = 0; i < 8; ++i)
            #pragma unroll
            for (int j = 0; j < 6; ++j)
                acc[i][j] += a4[i].x*w4[j].x + a4[i].y*w4[j].y
                           + a4[i].z*w4[j].z + a4[i].w*w4[j].w;
    }

    #pragma unroll
    for (int i = 0; i < 8; ++i) {
        int gr = row0 + ty*8 + i;
        int b = gr / NTOK, n = gr % NTOK;
        #pragma unroll
        for (int j = 0; j < 6; ++j) {
            int c = tx*6 + j;
            float v = acc[i][j] + bp[c];
            if (n == 0) dout[XOUT_SZ + (size_t)b*DIM + c] = v;
            else        dout[((size_t)b*NQ + (n-1))*DIM + c] = v;
        }
    }
}

// ---------------- launch ----------------
extern "C" void kernel_launch(void* const* d_in, const int* in_sizes, int n_in,
                              void* d_out, int out_size) {
    const float* x     = (const float*)d_in[0];
    const float* gt    = (const float*)d_in[1];
    const float* mask  = (const float*)d_in[2];
    const int*   ri    = (const int*)  d_in[3];
    const float* Wqkv  = (const float*)d_in[4];
    const float* bqkv  = (const float*)d_in[5];
    const float* Wproj = (const float*)d_in[6];
    const float* bproj = (const float*)d_in[7];
    const float* btab  = (const float*)d_in[8];
    float* out = (float*)d_out;

    cudaFuncSetAttribute(fused_attn_kernel, cudaFuncAttributeMaxDynamicSharedMemorySize, FUSED_SMEM);
    cudaFuncSetAttribute(proj_kernel,       cudaFuncAttributeMaxDynamicSharedMemorySize, GEMM_SMEM);

    {
        size_t total = (size_t)H*NW*NQ*BMSTR;
        bm_pre_kernel<<<(unsigned)((total + 255)/256), 256>>>(btab, ri, mask);
    }
    fused_attn_kernel<<<B_*H, 704, FUSED_SMEM>>>(x, gt, Wqkv, bqkv);
    proj_kernel<<<NROWS/128, 256, GEMM_SMEM>>>(Wproj, bproj, out);
}